// round 5
// baseline (speedup 1.0000x reference)
#include <cuda_runtime.h>
#include <math.h>

// features: (1, 50, 50, 1024) fp32 NHWC ; boxes: (1, 300, 4) fp32 [y1,x1,y2,x2]
// crop 14x14 bilinear, 2x2 max pool -> out (1, 300, 7, 7, 1024) fp32
// Boxes are uniform[0,1): sample coords in [0,49) so the +1 neighbor never
// clamps; rows/cols form contiguous runs -> base pointer + small offsets.

#define FH 50
#define FW 50
#define FC 1024
#define NBOX 300
#define CROP 14
#define PO 7
#define C4 (FC / 4)      // 256 float4 channel groups
#define TPB 256          // one channel group per thread
#define ROWS4 (FW * C4)  // float4 elements per feature row

__device__ __forceinline__ float4 wsum(const float4 tl, const float4 tr,
                                       const float4 bl, const float4 br,
                                       const float a, const float b)
{
    const float aa = 1.0f - a;
    const float bb = 1.0f - b;
    const float w0 = aa * bb, w1 = a * bb, w2 = aa * b, w3 = a * b;
    float4 v;
    v.x = fmaf(w3, br.x, fmaf(w2, bl.x, fmaf(w1, tr.x, w0 * tl.x)));
    v.y = fmaf(w3, br.y, fmaf(w2, bl.y, fmaf(w1, tr.y, w0 * tl.y)));
    v.z = fmaf(w3, br.z, fmaf(w2, bl.z, fmaf(w1, tr.z, w0 * tl.z)));
    v.w = fmaf(w3, br.w, fmaf(w2, bl.w, fmaf(w1, tr.w, w0 * tl.w)));
    return v;
}

__device__ __forceinline__ void max4(float4& m, const float4 v)
{
    m.x = fmaxf(m.x, v.x);
    m.y = fmaxf(m.y, v.y);
    m.z = fmaxf(m.z, v.z);
    m.w = fmaxf(m.w, v.w);
}

// YC/XC: 0 = sample1 rows == sample0 rows, 1 = chain (3 contiguous),
//        2 = disjoint (two contiguous pairs at runtime distance dr/dc).
template <int YC, int XC>
__device__ __forceinline__ void do_case(
    const float4* __restrict__ p,    // f4 + (r0*FW + c0)*C4 + c4
    float4* __restrict__ optr,       // out + blk*C4 + c4
    const int dr, const int dc,
    const float wy0, const float wy1, const float wx0, const float wx1)
{
    constexpr int NC = XC + 2;

    // Column offsets in float4 units (compile-time except XC==2).
    int coff[NC];
    coff[0] = 0;
    coff[1] = C4;
    if (XC == 1) { coff[2] = 2 * C4; }
    if (XC == 2) { coff[2] = dc * C4; coff[3] = coff[2] + C4; }

    // Column indices of the 2 x-samples' left corners.
    constexpr int XL1 = (XC == 0) ? 0 : ((XC == 1) ? 1 : 2);

    // ---- top band: rows 0,1 of the distinct-row run ----
    float4 a0[NC], a1[NC];
#pragma unroll
    for (int j = 0; j < NC; j++) a0[j] = p[coff[j]];
#pragma unroll
    for (int j = 0; j < NC; j++) a1[j] = p[ROWS4 + coff[j]];

    float4 m = wsum(a0[0], a0[1], a1[0], a1[1], wx0, wy0);
    max4(m, wsum(a0[XL1], a0[XL1 + 1], a1[XL1], a1[XL1 + 1], wx1, wy0));

    // ---- bottom band ----
    if (YC == 1) {
        // rows (1,2): top row = a1 (already loaded); load row 2 into a0.
#pragma unroll
        for (int j = 0; j < NC; j++) a0[j] = p[2 * ROWS4 + coff[j]];
        max4(m, wsum(a1[0], a1[1], a0[0], a0[1], wx0, wy1));
        max4(m, wsum(a1[XL1], a1[XL1 + 1], a0[XL1], a0[XL1 + 1], wx1, wy1));
    } else if (YC == 2) {
        // rows (dr, dr+1): reload both bands.
#pragma unroll
        for (int j = 0; j < NC; j++) a0[j] = p[dr * ROWS4 + coff[j]];
#pragma unroll
        for (int j = 0; j < NC; j++) a1[j] = p[dr * ROWS4 + ROWS4 + coff[j]];
        max4(m, wsum(a0[0], a0[1], a1[0], a1[1], wx0, wy1));
        max4(m, wsum(a0[XL1], a0[XL1 + 1], a1[XL1], a1[XL1 + 1], wx1, wy1));
    } else {
        // YC == 0: same rows, different wy.
        max4(m, wsum(a0[0], a0[1], a1[0], a1[1], wx0, wy1));
        max4(m, wsum(a0[XL1], a0[XL1 + 1], a1[XL1], a1[XL1 + 1], wx1, wy1));
    }

    *optr = m;
}

__global__ __launch_bounds__(TPB, 4)
void roi_pool_kernel(const float* __restrict__ feat,
                     const float* __restrict__ boxes,
                     float* __restrict__ out)
{
    const int blk = blockIdx.x;
    const int n   = blk / (PO * PO);
    const int p   = blk - n * (PO * PO);
    const int py  = p / PO;
    const int px  = p - py * PO;
    const int c4  = threadIdx.x;

    const float4 box = ((const float4*)boxes)[n];
    const float by1 = box.x, bx1 = box.y, by2 = box.z, bx2 = box.w;

    const float scale = 1.0f / (float)(CROP - 1);
    const float dy = (by2 - by1) * (float)(FH - 1) * scale;
    const float dx = (bx2 - bx1) * (float)(FW - 1) * scale;

    const float ys0 = by1 * (float)(FH - 1) + (float)(2 * py) * dy;
    const float ys1 = ys0 + dy;
    const float xs0 = bx1 * (float)(FW - 1) + (float)(2 * px) * dx;
    const float xs1 = xs0 + dx;

    const float yf0 = floorf(ys0), yf1 = floorf(ys1);
    const float xf0 = floorf(xs0), xf1 = floorf(xs1);
    const float wy0 = ys0 - yf0, wy1 = ys1 - yf1;
    const float wx0 = xs0 - xf0, wx1 = xs1 - xf1;

    // Clamps never fire on in-range data; they only bound memory accesses.
    const int r0 = min(max((int)yf0, 0), FH - 2);
    const int r2 = min(max((int)yf1, 0), FH - 2);
    const int c0 = min(max((int)xf0, 0), FW - 2);
    const int c2 = min(max((int)xf1, 0), FW - 2);

    const int dr = r2 - r0;
    const int dc = c2 - c0;
    const int yc = (dr == 0) ? 0 : ((dr == 1) ? 1 : 2);
    const int xc = (dc == 0) ? 0 : ((dc == 1) ? 1 : 2);

    const float4* __restrict__ pbase =
        (const float4*)feat + ((r0 * FW + c0) * C4 + c4);
    float4* __restrict__ optr = (float4*)out + (blk * C4 + c4);

    switch (yc * 3 + xc) {
        case 0: do_case<0,0>(pbase,optr,dr,dc,wy0,wy1,wx0,wx1); break;
        case 1: do_case<0,1>(pbase,optr,dr,dc,wy0,wy1,wx0,wx1); break;
        case 2: do_case<0,2>(pbase,optr,dr,dc,wy0,wy1,wx0,wx1); break;
        case 3: do_case<1,0>(pbase,optr,dr,dc,wy0,wy1,wx0,wx1); break;
        case 4: do_case<1,1>(pbase,optr,dr,dc,wy0,wy1,wx0,wx1); break;
        case 5: do_case<1,2>(pbase,optr,dr,dc,wy0,wy1,wx0,wx1); break;
        case 6: do_case<2,0>(pbase,optr,dr,dc,wy0,wy1,wx0,wx1); break;
        case 7: do_case<2,1>(pbase,optr,dr,dc,wy0,wy1,wx0,wx1); break;
        default:do_case<2,2>(pbase,optr,dr,dc,wy0,wy1,wx0,wx1); break;
    }
}

extern "C" void kernel_launch(void* const* d_in, const int* in_sizes, int n_in,
                              void* d_out, int out_size)
{
    const float* feat  = (const float*)d_in[0];
    const float* boxes = (const float*)d_in[1];
    float* out = (float*)d_out;

    roi_pool_kernel<<<NBOX * PO * PO, TPB>>>(feat, boxes, out);
}

// round 6
// speedup vs baseline: 1.1167x; 1.1167x over previous
#include <cuda_runtime.h>
#include <math.h>

// features: (1, 50, 50, 1024) fp32 NHWC ; boxes: (1, 300, 4) fp32 [y1,x1,y2,x2]
// crop 14x14 bilinear, 2x2 max pool -> out (1, 300, 7, 7, 1024) fp32
// Boxes are uniform[0,1): sample coords in [0,49) so +1 neighbors never clamp;
// rows/cols form contiguous runs -> base pointer + small/immediate offsets.

#define FH 50
#define FW 50
#define FC 1024
#define NBOX 300
#define CROP 14
#define PO 7
#define C4 (FC / 4)      // 256 float4 channel groups
#define TPB 128          // each thread handles channel groups c4 and c4+128
#define ROWS4 (FW * C4)  // float4 elements per feature row

__device__ __forceinline__ float4 wsum(const float4 tl, const float4 tr,
                                       const float4 bl, const float4 br,
                                       const float a, const float b)
{
    const float aa = 1.0f - a;
    const float bb = 1.0f - b;
    const float w0 = aa * bb, w1 = a * bb, w2 = aa * b, w3 = a * b;
    float4 v;
    v.x = fmaf(w3, br.x, fmaf(w2, bl.x, fmaf(w1, tr.x, w0 * tl.x)));
    v.y = fmaf(w3, br.y, fmaf(w2, bl.y, fmaf(w1, tr.y, w0 * tl.y)));
    v.z = fmaf(w3, br.z, fmaf(w2, bl.z, fmaf(w1, tr.z, w0 * tl.z)));
    v.w = fmaf(w3, br.w, fmaf(w2, bl.w, fmaf(w1, tr.w, w0 * tl.w)));
    return v;
}

__device__ __forceinline__ void max4(float4& m, const float4 v)
{
    m.x = fmaxf(m.x, v.x);
    m.y = fmaxf(m.y, v.y);
    m.z = fmaxf(m.z, v.z);
    m.w = fmaxf(m.w, v.w);
}

// YC/XC: 0 = sample1 rows == sample0 rows, 1 = chain (3 contiguous),
//        2 = disjoint (two contiguous pairs at runtime distance dr/dc).
// Banded gather: <= 2*NC float4 live at once (low regs), per channel group.
template <int YC, int XC>
__device__ __forceinline__ void do_case(
    const float4* __restrict__ p,    // f4 + (r0*FW + c0)*C4 + c4
    float4* __restrict__ optr,       // out + blk*C4 + c4
    const int dr, const int dc,
    const float wy0, const float wy1, const float wx0, const float wx1)
{
    constexpr int NC = XC + 2;
    constexpr int XL1 = (XC == 0) ? 0 : ((XC == 1) ? 1 : 2);

    int coff[NC];
    coff[0] = 0;
    coff[1] = C4;
    if (XC == 1) { coff[2] = 2 * C4; }
    if (XC == 2) { coff[2] = dc * C4; coff[3] = coff[2] + C4; }

#pragma unroll
    for (int cg = 0; cg < 2; cg++) {
        const int off = cg * TPB;    // +2048B immediate for second group

        // ---- top band: rows 0,1 ----
        float4 a0[NC], a1[NC];
#pragma unroll
        for (int j = 0; j < NC; j++) a0[j] = p[coff[j] + off];
#pragma unroll
        for (int j = 0; j < NC; j++) a1[j] = p[ROWS4 + coff[j] + off];

        float4 m = wsum(a0[0], a0[1], a1[0], a1[1], wx0, wy0);
        max4(m, wsum(a0[XL1], a0[XL1 + 1], a1[XL1], a1[XL1 + 1], wx1, wy0));

        // ---- bottom band ----
        if (YC == 1) {
            // rows (1,2): top row already in a1; load row 2 into a0.
#pragma unroll
            for (int j = 0; j < NC; j++) a0[j] = p[2 * ROWS4 + coff[j] + off];
            max4(m, wsum(a1[0], a1[1], a0[0], a0[1], wx0, wy1));
            max4(m, wsum(a1[XL1], a1[XL1 + 1], a0[XL1], a0[XL1 + 1], wx1, wy1));
        } else if (YC == 2) {
            // rows (dr, dr+1): reload both.
#pragma unroll
            for (int j = 0; j < NC; j++) a0[j] = p[dr * ROWS4 + coff[j] + off];
#pragma unroll
            for (int j = 0; j < NC; j++) a1[j] = p[(dr + 1) * ROWS4 + coff[j] + off];
            max4(m, wsum(a0[0], a0[1], a1[0], a1[1], wx0, wy1));
            max4(m, wsum(a0[XL1], a0[XL1 + 1], a1[XL1], a1[XL1 + 1], wx1, wy1));
        } else {
            // YC == 0: same rows, different wy.
            max4(m, wsum(a0[0], a0[1], a1[0], a1[1], wx0, wy1));
            max4(m, wsum(a0[XL1], a0[XL1 + 1], a1[XL1], a1[XL1 + 1], wx1, wy1));
        }

        optr[off] = m;
    }
}

__global__ __launch_bounds__(TPB, 8)
void roi_pool_kernel(const float* __restrict__ feat,
                     const float* __restrict__ boxes,
                     float* __restrict__ out)
{
    const int blk = blockIdx.x;
    const int n   = blk / (PO * PO);
    const int p   = blk - n * (PO * PO);
    const int py  = p / PO;
    const int px  = p - py * PO;
    const int c4  = threadIdx.x;

    const float4 box = ((const float4*)boxes)[n];
    const float by1 = box.x, bx1 = box.y, by2 = box.z, bx2 = box.w;

    const float scale = 1.0f / (float)(CROP - 1);
    const float dy = (by2 - by1) * (float)(FH - 1) * scale;
    const float dx = (bx2 - bx1) * (float)(FW - 1) * scale;

    const float ys0 = by1 * (float)(FH - 1) + (float)(2 * py) * dy;
    const float ys1 = ys0 + dy;
    const float xs0 = bx1 * (float)(FW - 1) + (float)(2 * px) * dx;
    const float xs1 = xs0 + dx;

    const float yf0 = floorf(ys0), yf1 = floorf(ys1);
    const float xf0 = floorf(xs0), xf1 = floorf(xs1);
    const float wy0 = ys0 - yf0, wy1 = ys1 - yf1;
    const float wx0 = xs0 - xf0, wx1 = xs1 - xf1;

    // Clamps never fire on in-range data; they only bound memory accesses.
    const int r0 = min(max((int)yf0, 0), FH - 2);
    const int r2 = min(max((int)yf1, 0), FH - 2);
    const int c0 = min(max((int)xf0, 0), FW - 2);
    const int c2 = min(max((int)xf1, 0), FW - 2);

    const int dr = r2 - r0;
    const int dc = c2 - c0;
    const int yc = (dr == 0) ? 0 : ((dr == 1) ? 1 : 2);
    const int xc = (dc == 0) ? 0 : ((dc == 1) ? 1 : 2);

    const float4* __restrict__ pbase =
        (const float4*)feat + ((r0 * FW + c0) * C4 + c4);
    float4* __restrict__ optr = (float4*)out + (blk * C4 + c4);

    switch (yc * 3 + xc) {
        case 0: do_case<0,0>(pbase,optr,dr,dc,wy0,wy1,wx0,wx1); break;
        case 1: do_case<0,1>(pbase,optr,dr,dc,wy0,wy1,wx0,wx1); break;
        case 2: do_case<0,2>(pbase,optr,dr,dc,wy0,wy1,wx0,wx1); break;
        case 3: do_case<1,0>(pbase,optr,dr,dc,wy0,wy1,wx0,wx1); break;
        case 4: do_case<1,1>(pbase,optr,dr,dc,wy0,wy1,wx0,wx1); break;
        case 5: do_case<1,2>(pbase,optr,dr,dc,wy0,wy1,wx0,wx1); break;
        case 6: do_case<2,0>(pbase,optr,dr,dc,wy0,wy1,wx0,wx1); break;
        case 7: do_case<2,1>(pbase,optr,dr,dc,wy0,wy1,wx0,wx1); break;
        default:do_case<2,2>(pbase,optr,dr,dc,wy0,wy1,wx0,wx1); break;
    }
}

extern "C" void kernel_launch(void* const* d_in, const int* in_sizes, int n_in,
                              void* d_out, int out_size)
{
    const float* feat  = (const float*)d_in[0];
    const float* boxes = (const float*)d_in[1];
    float* out = (float*)d_out;

    roi_pool_kernel<<<NBOX * PO * PO, TPB>>>(feat, boxes, out);
}